// round 1
// baseline (speedup 1.0000x reference)
#include <cuda_runtime.h>
#include <cstdint>

#define ROWS_TOTAL 32768
#define DIM 768
#define NF 16
#define NQ 8
#define BLOCK 128
#define ROWS_PB 128
#define KB 32
#define LDX 36
#define NCHUNK (DIM / KB)          /* 24 */
#define W_FLOATS (DIM * NF)        /* 12288 */
#define XS_FLOATS (ROWS_PB * LDX)  /* 4608 */
#define SMEM_BYTES ((W_FLOATS + 2 * XS_FLOATS) * 4)  /* 86016 */

__device__ __forceinline__ void ffma2(unsigned long long &d,
                                      unsigned long long a,
                                      unsigned long long b) {
    asm("fma.rn.f32x2 %0, %1, %2, %0;" : "+l"(d) : "l"(a), "l"(b));
}

__device__ __forceinline__ void cp_async16(float* dst, const float* src) {
    unsigned int d = (unsigned int)__cvta_generic_to_shared(dst);
    asm volatile("cp.async.cg.shared.global [%0], [%1], 16;" :: "r"(d), "l"(src));
}

__global__ __launch_bounds__(BLOCK)
void qadapter_kernel(const float* __restrict__ x,
                     const float* __restrict__ W,
                     const float* __restrict__ b,
                     const float* __restrict__ enc,
                     float* __restrict__ out) {
    extern __shared__ float smem[];
    float* W_s = smem;                 // 12288 floats, k-pair interleaved
    float* x_s = smem + W_FLOATS;      // 2 x 4608 floats

    const int tid = threadIdx.x;
    const int base = blockIdx.x * ROWS_PB;

    // ---- Stage W into smem, interleaved for f32x2 k-parity packing ----
    // W_s[k2*32 + 2c + (k&1)] = W[k*16 + c]  so that a ulonglong2 load at
    // float offset k2*32 + 4*c2 yields {(W[2k2][2c2],W[2k2+1][2c2]),
    //                                   (W[2k2][2c2+1],W[2k2+1][2c2+1])}
    for (int g = tid; g < W_FLOATS; g += BLOCK) {
        int k = g >> 4, c = g & 15;
        W_s[(k >> 1) * 32 + (c << 1) + (k & 1)] = W[g];
    }

    // ---- Prefetch x chunk 0 (coalesced: 8 float4 per thread) ----
    {
        const float* src = x + (size_t)base * DIM;
        float* dst = x_s;
        #pragma unroll
        for (int i = 0; i < 8; i++) {
            int pos = i * BLOCK + tid;
            int row = pos >> 3, c4 = (pos & 7) << 2;
            cp_async16(dst + row * LDX + c4, src + (size_t)row * DIM + c4);
        }
        asm volatile("cp.async.commit_group;");
    }

    unsigned long long acc[16];
    #pragma unroll
    for (int c = 0; c < 16; c++) acc[c] = 0ull;

    for (int ch = 0; ch < NCHUNK; ch++) {
        if (ch + 1 < NCHUNK) {
            const float* src = x + (size_t)base * DIM + (ch + 1) * KB;
            float* dst = x_s + ((ch + 1) & 1) * XS_FLOATS;
            #pragma unroll
            for (int i = 0; i < 8; i++) {
                int pos = i * BLOCK + tid;
                int row = pos >> 3, c4 = (pos & 7) << 2;
                cp_async16(dst + row * LDX + c4, src + (size_t)row * DIM + c4);
            }
            asm volatile("cp.async.commit_group;");
            asm volatile("cp.async.wait_group 1;");
        } else {
            asm volatile("cp.async.wait_group 0;");
        }
        __syncthreads();

        const float* xr = x_s + (ch & 1) * XS_FLOATS + tid * LDX;
        const float* wbase = W_s + ch * (KB * NF);  // = ch*512 floats
        #pragma unroll
        for (int kk = 0; kk < KB; kk += 4) {
            // x[k..k+3] for this thread's row: low/high f32x2 pairs
            ulonglong2 xv = *reinterpret_cast<const ulonglong2*>(xr + kk);
            const ulonglong2* w0 =
                reinterpret_cast<const ulonglong2*>(wbase + (kk >> 1) * 32);
            const ulonglong2* w1 =
                reinterpret_cast<const ulonglong2*>(wbase + ((kk >> 1) + 1) * 32);
            #pragma unroll
            for (int c2 = 0; c2 < 8; c2++) {
                ulonglong2 wa = w0[c2];   // broadcast across warp: 1 phase
                ffma2(acc[2 * c2],     xv.x, wa.x);
                ffma2(acc[2 * c2 + 1], xv.x, wa.y);
            }
            #pragma unroll
            for (int c2 = 0; c2 < 8; c2++) {
                ulonglong2 wb = w1[c2];
                ffma2(acc[2 * c2],     xv.y, wb.x);
                ffma2(acc[2 * c2 + 1], xv.y, wb.y);
            }
        }
        __syncthreads();
    }

    // ---- Epilogue: reduce k-parity halves, tanh, quantum encoding ----
    const int row = base + tid;
    float s[16];
    #pragma unroll
    for (int c = 0; c < 16; c++) {
        float lo = __uint_as_float((unsigned int)(acc[c] & 0xffffffffull));
        float hi = __uint_as_float((unsigned int)(acc[c] >> 32));
        float z = lo + hi + __ldg(&b[c]);
        float e = __expf(2.0f * z);                // tanh(z) = (e-1)/(e+1)
        s[c] = __fdividef(e - 1.0f, e + 1.0f);
    }
    float o[16];
    #pragma unroll
    for (int q = 0; q < NQ; q++) {
        float theta = s[2 * q]     + __ldg(&enc[q * 3 + 0]);
        float phi   = s[2 * q + 1] + __ldg(&enc[q * 3 + 1]);
        float sn, cs;
        __sincosf(0.5f * theta, &sn, &cs);
        o[2 * q]     = cs;
        o[2 * q + 1] = sn * __cosf(phi);
    }
    float4* op = reinterpret_cast<float4*>(out + (size_t)row * NF);
    #pragma unroll
    for (int i = 0; i < 4; i++)
        op[i] = make_float4(o[4 * i], o[4 * i + 1], o[4 * i + 2], o[4 * i + 3]);
}

extern "C" void kernel_launch(void* const* d_in, const int* in_sizes, int n_in,
                              void* d_out, int out_size) {
    const float* x   = (const float*)d_in[0];
    const float* W   = (const float*)d_in[1];
    const float* b   = (const float*)d_in[2];
    const float* enc = (const float*)d_in[3];
    float* out = (float*)d_out;

    cudaFuncSetAttribute(qadapter_kernel,
                         cudaFuncAttributeMaxDynamicSharedMemorySize, SMEM_BYTES);
    qadapter_kernel<<<ROWS_TOTAL / ROWS_PB, BLOCK, SMEM_BYTES>>>(x, W, b, enc, out);
}

// round 3
// speedup vs baseline: 1.2718x; 1.2718x over previous
#include <cuda_runtime.h>
#include <cstdint>

#define ROWS_TOTAL 32768
#define DIM 768
#define NF 16
#define NQ 8
#define BLOCK 128
#define ROWS_PB 128
#define KB 32
#define LDX 36                      /* 36 % 32 == 4 -> conflict-free vec4 */
#define NCHUNK (DIM / KB)           /* 24 */
#define W_FLOATS (DIM * NF)         /* 12288 = 48KB, natural row-major */
#define XS_FLOATS (ROWS_PB * LDX)   /* 4608 */
#define SMEM_BYTES ((W_FLOATS + 2 * XS_FLOATS) * 4)  /* 84.9KB -> 2 blocks/SM */

__device__ __forceinline__ void ffma2(unsigned long long &d,
                                      unsigned long long a,
                                      unsigned long long b) {
    asm("fma.rn.f32x2 %0, %1, %2, %0;" : "+l"(d) : "l"(a), "l"(b));
}

__device__ __forceinline__ unsigned long long splat(float v) {
    unsigned long long r;
    asm("mov.b64 %0, {%1, %1};" : "=l"(r) : "f"(v));
    return r;
}

__device__ __forceinline__ void cp_async16(float* dst, const float* src) {
    unsigned int d = (unsigned int)__cvta_generic_to_shared(dst);
    asm volatile("cp.async.cg.shared.global [%0], [%1], 16;" :: "r"(d), "l"(src));
}

__device__ __forceinline__ void stage_x(const float* __restrict__ x,
                                        float* __restrict__ dst,
                                        int base, int ch, int tid) {
    const float* src = x + (size_t)base * DIM + ch * KB;
    #pragma unroll
    for (int i = 0; i < 8; i++) {
        int pos = i * BLOCK + tid;
        int row = pos >> 3, c4 = (pos & 7) << 2;
        cp_async16(dst + row * LDX + c4, src + (size_t)row * DIM + c4);
    }
    asm volatile("cp.async.commit_group;");
}

__global__ __launch_bounds__(BLOCK)
void qadapter_kernel(const float* __restrict__ x,
                     const float* __restrict__ W,
                     const float* __restrict__ b,
                     const float* __restrict__ enc,
                     float* __restrict__ out) {
    extern __shared__ float smem[];
    float* W_s = smem;                 // 12288 floats, NATURAL row-major layout
    float* x_s = smem + W_FLOATS;      // 2 x 4608 floats

    const int tid = threadIdx.x;
    const int base = blockIdx.x * ROWS_PB;

    // ---- Stage W (natural copy, cp.async) : group 0 ----
    {
        const float4* Wsrc = reinterpret_cast<const float4*>(W);
        #pragma unroll
        for (int i = 0; i < 24; i++) {
            int g4 = i * BLOCK + tid;                   // 3072 float4 total
            cp_async16(W_s + g4 * 4, reinterpret_cast<const float*>(Wsrc + g4));
        }
        asm volatile("cp.async.commit_group;");
    }
    // ---- Prefetch x chunks 0 and 1 : groups 1, 2 ----
    stage_x(x, x_s, base, 0, tid);
    stage_x(x, x_s + XS_FLOATS, base, 1, tid);

    unsigned long long acc[8];          // acc[i]: lo = col 2i, hi = col 2i+1
    #pragma unroll
    for (int i = 0; i < 8; i++) acc[i] = 0ull;

    for (int ch = 0; ch < NCHUNK; ch++) {
        if (ch < NCHUNK - 1) asm volatile("cp.async.wait_group 1;");
        else                 asm volatile("cp.async.wait_group 0;");
        __syncthreads();

        const float* xr = x_s + (ch & 1) * XS_FLOATS + tid * LDX;
        const float* wc = W_s + ch * (KB * NF);

        #pragma unroll
        for (int kk = 0; kk < KB; kk += 4) {
            float4 xv = *reinterpret_cast<const float4*>(xr + kk);
            float xk[4] = {xv.x, xv.y, xv.z, xv.w};
            #pragma unroll
            for (int j = 0; j < 4; j++) {
                unsigned long long xs = splat(xk[j]);
                const ulonglong2* wp =
                    reinterpret_cast<const ulonglong2*>(wc + (kk + j) * NF);
                ulonglong2 w01 = wp[0];   // W[k][0..3]   (broadcast LDS.128)
                ulonglong2 w23 = wp[1];   // W[k][4..7]
                ulonglong2 w45 = wp[2];   // W[k][8..11]
                ulonglong2 w67 = wp[3];   // W[k][12..15]
                ffma2(acc[0], xs, w01.x);
                ffma2(acc[1], xs, w01.y);
                ffma2(acc[2], xs, w23.x);
                ffma2(acc[3], xs, w23.y);
                ffma2(acc[4], xs, w45.x);
                ffma2(acc[5], xs, w45.y);
                ffma2(acc[6], xs, w67.x);
                ffma2(acc[7], xs, w67.y);
            }
        }
        __syncthreads();
        if (ch + 2 < NCHUNK)
            stage_x(x, x_s + (ch & 1) * XS_FLOATS, base, ch + 2, tid);
    }

    // ---- Epilogue: bias + tanh + quantum encoding ----
    const int row = base + tid;
    float s[16];
    #pragma unroll
    for (int i = 0; i < 8; i++) {
        float lo = __uint_as_float((unsigned int)(acc[i] & 0xffffffffull));
        float hi = __uint_as_float((unsigned int)(acc[i] >> 32));
        float z0 = lo + __ldg(&b[2 * i]);
        float z1 = hi + __ldg(&b[2 * i + 1]);
        float e0 = __expf(2.0f * z0);
        float e1 = __expf(2.0f * z1);
        s[2 * i]     = __fdividef(e0 - 1.0f, e0 + 1.0f);
        s[2 * i + 1] = __fdividef(e1 - 1.0f, e1 + 1.0f);
    }
    float o[16];
    #pragma unroll
    for (int q = 0; q < NQ; q++) {
        float theta = s[2 * q]     + __ldg(&enc[q * 3 + 0]);
        float phi   = s[2 * q + 1] + __ldg(&enc[q * 3 + 1]);
        float sn, cs;
        __sincosf(0.5f * theta, &sn, &cs);
        o[2 * q]     = cs;
        o[2 * q + 1] = sn * __cosf(phi);
    }
    float4* op = reinterpret_cast<float4*>(out + (size_t)row * NF);
    #pragma unroll
    for (int i = 0; i < 4; i++)
        op[i] = make_float4(o[4 * i], o[4 * i + 1], o[4 * i + 2], o[4 * i + 3]);
}

extern "C" void kernel_launch(void* const* d_in, const int* in_sizes, int n_in,
                              void* d_out, int out_size) {
    const float* x   = (const float*)d_in[0];
    const float* W   = (const float*)d_in[1];
    const float* b   = (const float*)d_in[2];
    const float* enc = (const float*)d_in[3];
    float* out = (float*)d_out;

    cudaFuncSetAttribute(qadapter_kernel,
                         cudaFuncAttributeMaxDynamicSharedMemorySize, SMEM_BYTES);
    qadapter_kernel<<<ROWS_TOTAL / ROWS_PB, BLOCK, SMEM_BYTES>>>(x, W, b, enc, out);
}